// round 14
// baseline (speedup 1.0000x reference)
#include <cuda_runtime.h>
#include <math.h>

#define TTOT 50

// ---------------- constants / weights ----------------
__device__ float g_psp[32];       // device-computed fp64-exact, copied to c_psp
__device__ float g_ref[16];
__constant__ float c_psp[32];
__constant__ float c_ref[16];
__constant__ float c_wts[6160];   // w1 @0 (400), w2 @400 (1152), w3 @1552 (4608)

// ---------------- scratch (time-planar [T][N][C][H][W]) ----------------
__device__ float g_buf0[26214400];   // [50][4][2][256][256]   psp0 out (conv1 input)
__device__ float g_buf1[25806400];   // [50][4][8][127][127]   u1 -> p1 (in place)
__device__ float g_buf2[6350400];    // [50][4][8][63][63]     p2 (conv2 input)
__device__ float g_buf3[3276800];    // [50][4][16][32][32]    u2 -> p3 (in place)
__device__ float g_buf4[819200];     // [50][4][16][16][16]    p4 (conv3 input)
__device__ float g_buf5[409600];     // [50][4][32][8][8]      u3 -> p5 (in place)

// ---------------- init: fp64 kernel constants (match numpy exactly) ----------------
__global__ void init_consts() {
    int i = threadIdx.x;
    if (i < 32) g_psp[i] = (float)((i / 10.0) * exp(1.0 - i / 10.0));
    if (i < 16) g_ref[i] = (float)(-20.0 * (double)(i + 1) * exp(-(double)i));
}

__device__ __forceinline__ void ref_update(float* rb, int t) {
#pragma unroll
    for (int j = 0; j < 16; j++) rb[(t + 1 + j) & 15] += c_ref[j];
}

// Phase-2 psp: ILP independent ascending-k FMA chains (bit-identical per output
// to the validated sequential form; fmaf(0,kp,acc)=acc, fmaf(1,kp,acc)=rn(acc+kp)).
template<int ILP>
__device__ __forceinline__ void psp_phase2(const float* s, float* p, size_t S) {
#pragma unroll
    for (int t0 = 0; t0 < TTOT; t0 += ILP) {
        float acc[ILP];
#pragma unroll
        for (int i = 0; i < ILP; i++) acc[i] = 0.f;
#pragma unroll
        for (int k = 1; k < 32; k++) {
            float kp = c_psp[k];
#pragma unroll
            for (int i = 0; i < ILP; i++)
                if (k <= t0 + i) acc[i] = fmaf(s[t0 + i - k], kp, acc[i]);
        }
#pragma unroll
        for (int i = 0; i < ILP; i++) p[(size_t)(t0 + i) * S] = acc[i];
    }
}

// ---------------- psp0: [N,C,H,W,T] (binary) -> planar FIR, two-phase ----------------
__global__ void __launch_bounds__(256, 2) psp0_kernel(const float* __restrict__ in,
                                                      float* __restrict__ out) {
    int n = blockIdx.x * blockDim.x + threadIdx.x;
    if (n >= 524288) return;
    const float2* p = (const float2*)(in + (size_t)n * TTOT);
    float s[TTOT];
#pragma unroll
    for (int tt = 0; tt < TTOT / 2; tt++) {
        float2 x = __ldg(p + tt);
        s[2 * tt]     = (x.x > 0.5f) ? 1.0f : 0.0f;
        s[2 * tt + 1] = (x.y > 0.5f) ? 1.0f : 0.0f;
    }
    psp_phase2<10>(s, out + n, 524288);
}

// ---------------- fused spike -> psp, in-place, two-phase ----------------
__global__ void __launch_bounds__(256, 3) spike_psp_kernel(float* __restrict__ buf, int S) {
    int n = blockIdx.x * blockDim.x + threadIdx.x;
    if (n >= S) return;
    float rb[16];
#pragma unroll
    for (int j = 0; j < 16; j++) rb[j] = 0.f;
    float s[TTOT];
    float* p = buf + n;
    // phase 1: sequential spike generation
#pragma unroll
    for (int t = 0; t < TTOT; t++) {
        float v = p[(size_t)t * S] + rb[t & 15];
        rb[t & 15] = 0.f;
        bool sp = (v >= 10.0f);
        if (sp) ref_update(rb, t);
        s[t] = sp ? 1.0f : 0.0f;
    }
    // phase 2: independent psp outputs, 5-way ILP
    psp_phase2<5>(s, p, (size_t)S);
}

// ---------------- fused pool(2x2,s2,*2.75) -> spike -> psp, two-phase ----------------
template<int HI, int HO>
__global__ void __launch_bounds__(256, 2) pool_spike_psp_kernel(const float* __restrict__ in,
                                                                float* __restrict__ out,
                                                                int planes, int S_in, int S_out) {
    int idx = blockIdx.x * blockDim.x + threadIdx.x;
    int total = planes * HO * HO;
    if (idx >= total) return;
    int wo = idx % HO;
    int ho = (idx / HO) % HO;
    int pl = idx / (HO * HO);
    const float* p = in + (size_t)pl * HI * HI + (size_t)(2 * ho) * HI + 2 * wo;
    float* q = out + (size_t)pl * HO * HO + (size_t)ho * HO + wo;

    float rb[16];
#pragma unroll
    for (int j = 0; j < 16; j++) rb[j] = 0.f;
    float s[TTOT];
#pragma unroll
    for (int t = 0; t < TTOT; t++) {
        const float* pt = p + (size_t)t * S_in;
        float a = __ldg(pt);
        float b = __ldg(pt + 1);
        float c = __ldg(pt + HI);
        float d = __ldg(pt + HI + 1);
        float pooled = 2.75f * ((a + b) + (c + d));   // exact R1 expression
        float v = pooled + rb[t & 15];
        rb[t & 15] = 0.f;
        bool sp = (v >= 10.0f);
        if (sp) ref_update(rb, t);
        s[t] = sp ? 1.0f : 0.0f;
    }
    psp_phase2<10>(s, q, (size_t)S_out);
}

// ---------------- conv1 specialized: CI=2, K=5, s2 p1, 256->127, COG=8, WT=4 ----------------
// Vectorized input loads: wo0=4*wt so first index 8wt-1 === 3 (mod 4); the 11
// needed scalars live in 4 aligned float4s at base 8wt-4. OOB vectors cover
// only invalid indices -> zero-fill reproduces the scalar bounds check exactly.
__global__ void __launch_bounds__(256) conv1_kernel(const float* __restrict__ in,
                                                    float* __restrict__ out) {
    constexpr int HI = 256, HO = 127, WOT = 32;
    constexpr int TOTAL = 200 * HO * WOT;
    int idx = blockIdx.x * blockDim.x + threadIdx.x;
    if (idx >= TOTAL) return;
    int wt  = idx % WOT;
    int r   = idx / WOT;
    int ho  = r % HO;
    int img = r / HO;
    int wo0 = wt * 4;
    const float* inb = in + (size_t)img * 2 * HI * HI;

    float acc[8][4];
#pragma unroll
    for (int c = 0; c < 8; c++)
#pragma unroll
        for (int j = 0; j < 4; j++) acc[c][j] = 0.f;

    int base = 8 * wt - 4;   // aligned float4 base for this thread's window
#pragma unroll
    for (int ci = 0; ci < 2; ci++) {
#pragma unroll
        for (int kh = 0; kh < 5; kh++) {
            int ih = 2 * ho - 1 + kh;
            if (ih < 0 || ih >= HI) continue;
            const float* row = inb + (size_t)(ci * HI + ih) * HI;
            float4 vec[4];
#pragma unroll
            for (int jv = 0; jv < 4; jv++) {
                int b = base + 4 * jv;
                if (b >= 0 && b + 3 < HI)
                    vec[jv] = __ldg((const float4*)(row + b));
                else
                    vec[jv] = make_float4(0.f, 0.f, 0.f, 0.f);
            }
            float xv[11];
#pragma unroll
            for (int v = 0; v < 11; v++) {
                int pos = v + 3;
                const float* vf = (const float*)&vec[pos >> 2];
                xv[v] = vf[pos & 3];
            }
#pragma unroll
            for (int kw = 0; kw < 5; kw++) {
#pragma unroll
                for (int c = 0; c < 8; c++) {
                    float w = c_wts[((c * 2 + ci) * 5 + kh) * 5 + kw];
#pragma unroll
                    for (int j = 0; j < 4; j++)
                        acc[c][j] = fmaf(xv[2 * j + kw], w, acc[c][j]);
                }
            }
        }
    }
#pragma unroll
    for (int c = 0; c < 8; c++) {
        size_t ob = ((size_t)(img * 8 + c) * HO + ho) * HO;
#pragma unroll
        for (int j = 0; j < 4; j++)
            if (wo0 + j < HO) out[ob + wo0 + j] = acc[c][j];
    }
}

// ---------------- generic conv: stride-2, pad-1; register-tiled COG x WT ----------------
template<int CI, int CO, int COG, int HI, int HO, int K, int WOFF, int WT>
__global__ void __launch_bounds__(256) conv_kernel(const float* __restrict__ in,
                                                   float* __restrict__ out) {
    constexpr int WOT  = (HO + WT - 1) / WT;
    constexpr int NCOG = CO / COG;
    constexpr int NV   = 2 * (WT - 1) + K;
    constexpr int TOTAL = 200 * NCOG * HO * WOT;   // 200 = T*N
    int idx = blockIdx.x * blockDim.x + threadIdx.x;
    if (idx >= TOTAL) return;
    int wt  = idx % WOT;
    int r   = idx / WOT;
    int ho  = r % HO;  r /= HO;
    int cog = r % NCOG; r /= NCOG;
    int img = r;
    int wo0 = wt * WT;
    const float* inb = in + (size_t)img * CI * HI * HI;

    float acc[COG][WT];
#pragma unroll
    for (int c = 0; c < COG; c++)
#pragma unroll
        for (int j = 0; j < WT; j++) acc[c][j] = 0.f;

#pragma unroll
    for (int ci = 0; ci < CI; ci++) {
#pragma unroll
        for (int kh = 0; kh < K; kh++) {
            int ih = 2 * ho - 1 + kh;
            if (ih < 0 || ih >= HI) continue;
            const float* row = inb + (size_t)(ci * HI + ih) * HI;
            float xv[NV];
#pragma unroll
            for (int v = 0; v < NV; v++) {
                int iw = 2 * wo0 - 1 + v;
                xv[v] = (iw >= 0 && iw < HI) ? __ldg(row + iw) : 0.f;
            }
#pragma unroll
            for (int kw = 0; kw < K; kw++) {
#pragma unroll
                for (int c = 0; c < COG; c++) {
                    float w = c_wts[WOFF + (((cog * COG + c) * CI + ci) * K + kh) * K + kw];
#pragma unroll
                    for (int j = 0; j < WT; j++)
                        acc[c][j] = fmaf(xv[2 * j + kw], w, acc[c][j]);
                }
            }
        }
    }
#pragma unroll
    for (int c = 0; c < COG; c++) {
        int co = cog * COG + c;
        size_t ob = ((size_t)(img * CO + co) * HO + ho) * HO;
#pragma unroll
        for (int j = 0; j < WT; j++)
            if (wo0 + j < HO) out[ob + wo0 + j] = acc[c][j];
    }
}

// ---------------- FC head: one warp per (n,o,t) ----------------
__global__ void fc_kernel(const float* __restrict__ u, const float* __restrict__ wfc,
                          float* __restrict__ out) {
    int gw   = (blockIdx.x * blockDim.x + threadIdx.x) >> 5;
    int lane = threadIdx.x & 31;
    if (gw >= 400) return;
    int t  = gw % 50;
    int no = gw / 50;            // n*2+o
    int o  = no & 1;
    int n  = no >> 1;
    const float* ub = u + t * 8192 + n * 2048;
    const float* wb = wfc + o * 2048;
    float acc = 0.f;
#pragma unroll 8
    for (int i = lane; i < 2048; i += 32)
        acc = fmaf(__ldg(ub + i), __ldg(wb + i), acc);
#pragma unroll
    for (int off = 16; off; off >>= 1) acc += __shfl_xor_sync(0xffffffffu, acc, off);
    if (lane == 0) out[no * 50 + t] = acc;
}

// ---------------- final spike, in-place on d_out ([n][o][t]) ----------------
__global__ void spike_last_kernel(float* __restrict__ buf) {
    int n = threadIdx.x;
    if (n >= 8) return;
    float rb[16];
#pragma unroll
    for (int j = 0; j < 16; j++) rb[j] = 0.f;
    float* p = buf + n * 50;
#pragma unroll
    for (int t = 0; t < TTOT; t++) {
        float v = p[t] + rb[t & 15];
        rb[t & 15] = 0.f;
        float s;
        if (v >= 10.0f) {
            s = 1.0f;
            ref_update(rb, t);
        } else {
            s = 0.0f;
        }
        p[t] = s;
    }
}

static inline int cdiv(int a, int b) { return (a + b - 1) / b; }

extern "C" void kernel_launch(void* const* d_in, const int* in_sizes, int n_in,
                              void* d_out, int out_size) {
    const float* x_in = (const float*)d_in[0];
    const float* wfc  = (const float*)d_in[4];

    float *b0, *b1, *b2, *b3, *b4, *b5, *gp, *gr;
    cudaGetSymbolAddress((void**)&b0, g_buf0);
    cudaGetSymbolAddress((void**)&b1, g_buf1);
    cudaGetSymbolAddress((void**)&b2, g_buf2);
    cudaGetSymbolAddress((void**)&b3, g_buf3);
    cudaGetSymbolAddress((void**)&b4, g_buf4);
    cudaGetSymbolAddress((void**)&b5, g_buf5);
    cudaGetSymbolAddress((void**)&gp, g_psp);
    cudaGetSymbolAddress((void**)&gr, g_ref);

    // weights -> constant memory (D2D, graph-capturable)
    cudaMemcpyToSymbolAsync(c_wts, d_in[1], 400  * sizeof(float), 0,    cudaMemcpyDeviceToDevice, 0);
    cudaMemcpyToSymbolAsync(c_wts, d_in[2], 1152 * sizeof(float), 1600, cudaMemcpyDeviceToDevice, 0);
    cudaMemcpyToSymbolAsync(c_wts, d_in[3], 4608 * sizeof(float), 6208, cudaMemcpyDeviceToDevice, 0);

    // fp64-exact psp/ref tables: compute on device, then stage into __constant__
    init_consts<<<1, 32>>>();
    cudaMemcpyToSymbolAsync(c_psp, gp, 32 * sizeof(float), 0, cudaMemcpyDeviceToDevice, 0);
    cudaMemcpyToSymbolAsync(c_ref, gr, 16 * sizeof(float), 0, cudaMemcpyDeviceToDevice, 0);

    // L1: psp0 -> conv1(2->8, k5 s2 p1, 256->127, vectorized) -> [spike+psp]
    psp0_kernel<<<cdiv(524288, 256), 256>>>(x_in, b0);
    conv1_kernel<<<cdiv(200 * 127 * 32, 256), 256>>>(b0, b1);
    spike_psp_kernel<<<cdiv(516128, 256), 256>>>(b1, 516128);

    // L2: [pool+spike+psp] 127->63
    pool_spike_psp_kernel<127, 63><<<cdiv(32 * 63 * 63, 256), 256>>>(b1, b2, 32, 516128, 127008);

    // L3: conv2(8->16, k3 s2 p1, 63->32, WT=2) -> [spike+psp]
    conv_kernel<8, 16, 16, 63, 32, 3, 400, 2><<<cdiv(200 * 32 * 16, 256), 256>>>(b2, b3);
    spike_psp_kernel<<<cdiv(65536, 256), 256>>>(b3, 65536);

    // L4: [pool+spike+psp] 32->16
    pool_spike_psp_kernel<32, 16><<<cdiv(64 * 16 * 16, 256), 256>>>(b3, b4, 64, 65536, 16384);

    // L5: conv3(16->32, k3 s2 p1, 16->8) -> [spike+psp]
    conv_kernel<16, 32, 8, 16, 8, 3, 1552, 2><<<cdiv(200 * 4 * 8 * 4, 256), 256>>>(b4, b5);
    spike_psp_kernel<<<cdiv(8192, 256), 256>>>(b5, 8192);

    // head: FC -> final spike (in-place on d_out)
    fc_kernel<<<100, 128>>>(b5, wfc, (float*)d_out);
    spike_last_kernel<<<1, 8>>>((float*)d_out);
}

// round 15
// speedup vs baseline: 1.4518x; 1.4518x over previous
#include <cuda_runtime.h>
#include <math.h>

#define TTOT 50

// ---------------- constants / weights ----------------
__device__ float g_psp[32];       // device-computed fp64-exact, copied to c_psp
__device__ float g_ref[16];
__constant__ float c_psp[32];
__constant__ float c_ref[16];
__constant__ float c_wts[6160];   // w1 @0 (400), w2 @400 (1152), w3 @1552 (4608)

// ---------------- scratch (time-planar [T][N][C][H][W]) ----------------
__device__ float g_buf0[26214400];   // [50][4][2][256][256]   psp0 out (conv1 input)
__device__ float g_buf1[25806400];   // [50][4][8][127][127]   u1 -> p1 (in place)
__device__ float g_buf2[6350400];    // [50][4][8][63][63]     p2 (conv2 input)
__device__ float g_buf3[3276800];    // [50][4][16][32][32]    u2 -> p3 (in place)
__device__ float g_buf4[819200];     // [50][4][16][16][16]    p4 (conv3 input)
__device__ float g_buf5[409600];     // [50][4][32][8][8]      u3 -> p5 (in place)

// ---------------- init: fp64 kernel constants (match numpy exactly) ----------------
__global__ void init_consts() {
    int i = threadIdx.x;
    if (i < 32) g_psp[i] = (float)((i / 10.0) * exp(1.0 - i / 10.0));
    if (i < 16) g_ref[i] = (float)(-20.0 * (double)(i + 1) * exp(-(double)i));
}

__device__ __forceinline__ void ref_update(float* rb, int t) {
#pragma unroll
    for (int j = 0; j < 16; j++) rb[(t + 1 + j) & 15] += c_ref[j];
}

// Phase-2 psp: ILP independent ascending-k FMA chains (bit-identical per output
// to the validated sequential form; fmaf(0,kp,acc)=acc, fmaf(1,kp,acc)=rn(acc+kp)).
template<int ILP>
__device__ __forceinline__ void psp_phase2(const float* s, float* p, size_t S) {
#pragma unroll
    for (int t0 = 0; t0 < TTOT; t0 += ILP) {
        float acc[ILP];
#pragma unroll
        for (int i = 0; i < ILP; i++) acc[i] = 0.f;
#pragma unroll
        for (int k = 1; k < 32; k++) {
            float kp = c_psp[k];
#pragma unroll
            for (int i = 0; i < ILP; i++)
                if (k <= t0 + i) acc[i] = fmaf(s[t0 + i - k], kp, acc[i]);
        }
#pragma unroll
        for (int i = 0; i < ILP; i++) p[(size_t)(t0 + i) * S] = acc[i];
    }
}

// ---------------- psp0: [N,C,H,W,T] (binary) -> planar FIR, two-phase ----------------
__global__ void __launch_bounds__(256, 2) psp0_kernel(const float* __restrict__ in,
                                                      float* __restrict__ out) {
    int n = blockIdx.x * blockDim.x + threadIdx.x;
    if (n >= 524288) return;
    const float2* p = (const float2*)(in + (size_t)n * TTOT);
    float s[TTOT];
#pragma unroll
    for (int tt = 0; tt < TTOT / 2; tt++) {
        float2 x = __ldg(p + tt);
        s[2 * tt]     = (x.x > 0.5f) ? 1.0f : 0.0f;
        s[2 * tt + 1] = (x.y > 0.5f) ? 1.0f : 0.0f;
    }
    psp_phase2<10>(s, out + n, 524288);
}

// ---------------- fused spike -> psp, in-place, two-phase ----------------
__global__ void __launch_bounds__(256, 2) spike_psp_kernel(float* __restrict__ buf, int S) {
    int n = blockIdx.x * blockDim.x + threadIdx.x;
    if (n >= S) return;
    float rb[16];
#pragma unroll
    for (int j = 0; j < 16; j++) rb[j] = 0.f;
    float s[TTOT];
    float* p = buf + n;
    // phase 1: sequential spike generation
#pragma unroll
    for (int t = 0; t < TTOT; t++) {
        float v = p[(size_t)t * S] + rb[t & 15];
        rb[t & 15] = 0.f;
        bool sp = (v >= 10.0f);
        if (sp) ref_update(rb, t);
        s[t] = sp ? 1.0f : 0.0f;
    }
    // phase 2: independent psp outputs, 10-way ILP
    psp_phase2<10>(s, p, (size_t)S);
}

// ---------------- fused pool(2x2,s2,*2.75) -> spike -> psp, two-phase ----------------
template<int HI, int HO>
__global__ void __launch_bounds__(256, 2) pool_spike_psp_kernel(const float* __restrict__ in,
                                                                float* __restrict__ out,
                                                                int planes, int S_in, int S_out) {
    int idx = blockIdx.x * blockDim.x + threadIdx.x;
    int total = planes * HO * HO;
    if (idx >= total) return;
    int wo = idx % HO;
    int ho = (idx / HO) % HO;
    int pl = idx / (HO * HO);
    const float* p = in + (size_t)pl * HI * HI + (size_t)(2 * ho) * HI + 2 * wo;
    float* q = out + (size_t)pl * HO * HO + (size_t)ho * HO + wo;

    float rb[16];
#pragma unroll
    for (int j = 0; j < 16; j++) rb[j] = 0.f;
    float s[TTOT];
#pragma unroll
    for (int t = 0; t < TTOT; t++) {
        const float* pt = p + (size_t)t * S_in;
        float a = __ldg(pt);
        float b = __ldg(pt + 1);
        float c = __ldg(pt + HI);
        float d = __ldg(pt + HI + 1);
        float pooled = 2.75f * ((a + b) + (c + d));   // exact R1 expression
        float v = pooled + rb[t & 15];
        rb[t & 15] = 0.f;
        bool sp = (v >= 10.0f);
        if (sp) ref_update(rb, t);
        s[t] = sp ? 1.0f : 0.0f;
    }
    psp_phase2<10>(s, q, (size_t)S_out);
}

// ---------------- conv1 specialized: CI=2, K=5, s2 p1, 256->127, COG=8, WT=4 ----------------
// Window iw = 8wt-1 .. 8wt+9 loaded as: 1 scalar (8wt-1) + 2 aligned float4
// (8wt, 8wt+4) + 1 aligned float2 (8wt+8). Explicit .x/.y/.z/.w extraction only
// (no address-of on register data). Edge zero-fills reproduce padding exactly;
// the zeroed float2 at wt=31 only feeds output column 127, which is discarded.
__global__ void __launch_bounds__(256) conv1_kernel(const float* __restrict__ in,
                                                    float* __restrict__ out) {
    constexpr int HI = 256, HO = 127, WOT = 32;
    constexpr int TOTAL = 200 * HO * WOT;
    int idx = blockIdx.x * blockDim.x + threadIdx.x;
    if (idx >= TOTAL) return;
    int wt  = idx % WOT;
    int r   = idx / WOT;
    int ho  = r % HO;
    int img = r / HO;
    int wo0 = wt * 4;
    const float* inb = in + (size_t)img * 2 * HI * HI;

    float acc[8][4];
#pragma unroll
    for (int c = 0; c < 8; c++)
#pragma unroll
        for (int j = 0; j < 4; j++) acc[c][j] = 0.f;

    int b0 = 8 * wt;
#pragma unroll
    for (int ci = 0; ci < 2; ci++) {
#pragma unroll
        for (int kh = 0; kh < 5; kh++) {
            int ih = 2 * ho - 1 + kh;
            if (ih < 0 || ih >= HI) continue;
            const float* row = inb + (size_t)(ci * HI + ih) * HI;
            float  x0 = (wt > 0) ? __ldg(row + b0 - 1) : 0.f;
            float4 v1 = __ldg((const float4*)(row + b0));
            float4 v2 = __ldg((const float4*)(row + b0 + 4));
            float2 v3 = (wt < 31) ? __ldg((const float2*)(row + b0 + 8))
                                  : make_float2(0.f, 0.f);
            float xv[11];
            xv[0]  = x0;
            xv[1]  = v1.x;  xv[2]  = v1.y;  xv[3]  = v1.z;  xv[4]  = v1.w;
            xv[5]  = v2.x;  xv[6]  = v2.y;  xv[7]  = v2.z;  xv[8]  = v2.w;
            xv[9]  = v3.x;  xv[10] = v3.y;
#pragma unroll
            for (int kw = 0; kw < 5; kw++) {
#pragma unroll
                for (int c = 0; c < 8; c++) {
                    float w = c_wts[((c * 2 + ci) * 5 + kh) * 5 + kw];
#pragma unroll
                    for (int j = 0; j < 4; j++)
                        acc[c][j] = fmaf(xv[2 * j + kw], w, acc[c][j]);
                }
            }
        }
    }
#pragma unroll
    for (int c = 0; c < 8; c++) {
        size_t ob = ((size_t)(img * 8 + c) * HO + ho) * HO;
#pragma unroll
        for (int j = 0; j < 4; j++)
            if (wo0 + j < HO) out[ob + wo0 + j] = acc[c][j];
    }
}

// ---------------- generic conv: stride-2, pad-1; register-tiled COG x WT ----------------
template<int CI, int CO, int COG, int HI, int HO, int K, int WOFF, int WT>
__global__ void __launch_bounds__(256) conv_kernel(const float* __restrict__ in,
                                                   float* __restrict__ out) {
    constexpr int WOT  = (HO + WT - 1) / WT;
    constexpr int NCOG = CO / COG;
    constexpr int NV   = 2 * (WT - 1) + K;
    constexpr int TOTAL = 200 * NCOG * HO * WOT;   // 200 = T*N
    int idx = blockIdx.x * blockDim.x + threadIdx.x;
    if (idx >= TOTAL) return;
    int wt  = idx % WOT;
    int r   = idx / WOT;
    int ho  = r % HO;  r /= HO;
    int cog = r % NCOG; r /= NCOG;
    int img = r;
    int wo0 = wt * WT;
    const float* inb = in + (size_t)img * CI * HI * HI;

    float acc[COG][WT];
#pragma unroll
    for (int c = 0; c < COG; c++)
#pragma unroll
        for (int j = 0; j < WT; j++) acc[c][j] = 0.f;

#pragma unroll
    for (int ci = 0; ci < CI; ci++) {
#pragma unroll
        for (int kh = 0; kh < K; kh++) {
            int ih = 2 * ho - 1 + kh;
            if (ih < 0 || ih >= HI) continue;
            const float* row = inb + (size_t)(ci * HI + ih) * HI;
            float xv[NV];
#pragma unroll
            for (int v = 0; v < NV; v++) {
                int iw = 2 * wo0 - 1 + v;
                xv[v] = (iw >= 0 && iw < HI) ? __ldg(row + iw) : 0.f;
            }
#pragma unroll
            for (int kw = 0; kw < K; kw++) {
#pragma unroll
                for (int c = 0; c < COG; c++) {
                    float w = c_wts[WOFF + (((cog * COG + c) * CI + ci) * K + kh) * K + kw];
#pragma unroll
                    for (int j = 0; j < WT; j++)
                        acc[c][j] = fmaf(xv[2 * j + kw], w, acc[c][j]);
                }
            }
        }
    }
#pragma unroll
    for (int c = 0; c < COG; c++) {
        int co = cog * COG + c;
        size_t ob = ((size_t)(img * CO + co) * HO + ho) * HO;
#pragma unroll
        for (int j = 0; j < WT; j++)
            if (wo0 + j < HO) out[ob + wo0 + j] = acc[c][j];
    }
}

// ---------------- FC head: one warp per (n,o,t) ----------------
__global__ void fc_kernel(const float* __restrict__ u, const float* __restrict__ wfc,
                          float* __restrict__ out) {
    int gw   = (blockIdx.x * blockDim.x + threadIdx.x) >> 5;
    int lane = threadIdx.x & 31;
    if (gw >= 400) return;
    int t  = gw % 50;
    int no = gw / 50;            // n*2+o
    int o  = no & 1;
    int n  = no >> 1;
    const float* ub = u + t * 8192 + n * 2048;
    const float* wb = wfc + o * 2048;
    float acc = 0.f;
#pragma unroll 8
    for (int i = lane; i < 2048; i += 32)
        acc = fmaf(__ldg(ub + i), __ldg(wb + i), acc);
#pragma unroll
    for (int off = 16; off; off >>= 1) acc += __shfl_xor_sync(0xffffffffu, acc, off);
    if (lane == 0) out[no * 50 + t] = acc;
}

// ---------------- final spike, in-place on d_out ([n][o][t]) ----------------
__global__ void spike_last_kernel(float* __restrict__ buf) {
    int n = threadIdx.x;
    if (n >= 8) return;
    float rb[16];
#pragma unroll
    for (int j = 0; j < 16; j++) rb[j] = 0.f;
    float* p = buf + n * 50;
#pragma unroll
    for (int t = 0; t < TTOT; t++) {
        float v = p[t] + rb[t & 15];
        rb[t & 15] = 0.f;
        float s;
        if (v >= 10.0f) {
            s = 1.0f;
            ref_update(rb, t);
        } else {
            s = 0.0f;
        }
        p[t] = s;
    }
}

static inline int cdiv(int a, int b) { return (a + b - 1) / b; }

extern "C" void kernel_launch(void* const* d_in, const int* in_sizes, int n_in,
                              void* d_out, int out_size) {
    const float* x_in = (const float*)d_in[0];
    const float* wfc  = (const float*)d_in[4];

    float *b0, *b1, *b2, *b3, *b4, *b5, *gp, *gr;
    cudaGetSymbolAddress((void**)&b0, g_buf0);
    cudaGetSymbolAddress((void**)&b1, g_buf1);
    cudaGetSymbolAddress((void**)&b2, g_buf2);
    cudaGetSymbolAddress((void**)&b3, g_buf3);
    cudaGetSymbolAddress((void**)&b4, g_buf4);
    cudaGetSymbolAddress((void**)&b5, g_buf5);
    cudaGetSymbolAddress((void**)&gp, g_psp);
    cudaGetSymbolAddress((void**)&gr, g_ref);

    // weights -> constant memory (D2D, graph-capturable)
    cudaMemcpyToSymbolAsync(c_wts, d_in[1], 400  * sizeof(float), 0,    cudaMemcpyDeviceToDevice, 0);
    cudaMemcpyToSymbolAsync(c_wts, d_in[2], 1152 * sizeof(float), 1600, cudaMemcpyDeviceToDevice, 0);
    cudaMemcpyToSymbolAsync(c_wts, d_in[3], 4608 * sizeof(float), 6208, cudaMemcpyDeviceToDevice, 0);

    // fp64-exact psp/ref tables: compute on device, then stage into __constant__
    init_consts<<<1, 32>>>();
    cudaMemcpyToSymbolAsync(c_psp, gp, 32 * sizeof(float), 0, cudaMemcpyDeviceToDevice, 0);
    cudaMemcpyToSymbolAsync(c_ref, gr, 16 * sizeof(float), 0, cudaMemcpyDeviceToDevice, 0);

    // L1: psp0 -> conv1(2->8, k5 s2 p1, 256->127, vectorized loads) -> [spike+psp]
    psp0_kernel<<<cdiv(524288, 256), 256>>>(x_in, b0);
    conv1_kernel<<<cdiv(200 * 127 * 32, 256), 256>>>(b0, b1);
    spike_psp_kernel<<<cdiv(516128, 256), 256>>>(b1, 516128);

    // L2: [pool+spike+psp] 127->63
    pool_spike_psp_kernel<127, 63><<<cdiv(32 * 63 * 63, 256), 256>>>(b1, b2, 32, 516128, 127008);

    // L3: conv2(8->16, k3 s2 p1, 63->32, WT=2) -> [spike+psp]
    conv_kernel<8, 16, 16, 63, 32, 3, 400, 2><<<cdiv(200 * 32 * 16, 256), 256>>>(b2, b3);
    spike_psp_kernel<<<cdiv(65536, 256), 256>>>(b3, 65536);

    // L4: [pool+spike+psp] 32->16
    pool_spike_psp_kernel<32, 16><<<cdiv(64 * 16 * 16, 256), 256>>>(b3, b4, 64, 65536, 16384);

    // L5: conv3(16->32, k3 s2 p1, 16->8) -> [spike+psp]
    conv_kernel<16, 32, 8, 16, 8, 3, 1552, 2><<<cdiv(200 * 4 * 8 * 4, 256), 256>>>(b4, b5);
    spike_psp_kernel<<<cdiv(8192, 256), 256>>>(b5, 8192);

    // head: FC -> final spike (in-place on d_out)
    fc_kernel<<<100, 128>>>(b5, wfc, (float*)d_out);
    spike_last_kernel<<<1, 8>>>((float*)d_out);
}